// round 1
// baseline (speedup 1.0000x reference)
#include <cuda_runtime.h>
#include <cstdint>

typedef unsigned long long ull;

#define CL 4            // cluster size (hidx split)
#define BT 16           // batches per cluster
#define TS_LEN 512
#define BTOT 512
#define HD 256
#define THREADS 256
#define KCH 64          // k chunk per k-split group (256/4)
#define RSTRIDE 66      // padded smem reduce row stride (floats) to dodge bank conflicts
#define SMEM_FLOATS (2*256*16 + 256*RSTRIDE)
#define SMEM_BYTES (SMEM_FLOATS*4)

// -------- scratch (device globals; no allocations allowed) --------
__device__ float4 g_Wq4[CL*256*64];       // [r][k][l] -> {Wi,Wf,Wg,Wo} packed, transposed W_hh
__device__ float  g_wih[CL*4*64];         // [(r*4+g)*64+l]
__device__ float  g_bias[CL*4*64];        // b_ih + b_hh, same layout
__device__ float  g_tsT[TS_LEN*BTOT];     // transposed time series [t][b]
__device__ float  g_part[CL*BTOT];        // per-rank output partials

// -------- helpers --------
__device__ __forceinline__ ull fma2(ull a, ull b, ull c){
    ull d; asm("fma.rn.f32x2 %0, %1, %2, %3;" : "=l"(d) : "l"(a), "l"(b), "l"(c)); return d;
}
__device__ __forceinline__ ull pack2(float x, float y){
    ull r; asm("mov.b64 %0, {%1, %2};" : "=l"(r) : "f"(x), "f"(y)); return r;
}
__device__ __forceinline__ float sigf(float x){
    float e = __expf(-x); return __fdividef(1.f, 1.f + e);
}
__device__ __forceinline__ float tanha(float x){
    float ax = fabsf(x);
    float e = __expf(-2.f*ax);                 // in (0,1], no overflow
    float t = __fdividef(1.f - e, 1.f + e);
    return copysignf(t, x);
}
__device__ __forceinline__ uint32_t smem_u32(const void* p){
    uint32_t a;
    asm("{ .reg .u64 t; cvta.to.shared.u64 t, %1; cvt.u32.u64 %0, t; }" : "=r"(a) : "l"(p));
    return a;
}
__device__ __forceinline__ uint32_t mapa_r(uint32_t addr, uint32_t rank){
    uint32_t r; asm("mapa.shared::cluster.u32 %0, %1, %2;" : "=r"(r) : "r"(addr), "r"(rank)); return r;
}

// -------- prep: transpose/pack weights, bias, time series --------
__global__ void prep_kernel(const float* __restrict__ ts, const float* __restrict__ W_ih,
                            const float* __restrict__ W_hh, const float* __restrict__ b_ih,
                            const float* __restrict__ b_hh){
    int stride = gridDim.x * blockDim.x;
    int i0 = blockIdx.x * blockDim.x + threadIdx.x;
    float* Wq = (float*)g_Wq4;
    for (int idx = i0; idx < CL*256*64*4; idx += stride){
        int g = idx & 3, l = (idx>>2)&63, k = (idx>>8)&255, r = idx>>16;
        Wq[idx] = W_hh[(g*256 + r*64 + l)*256 + k];
    }
    for (int idx = i0; idx < CL*4*64; idx += stride){
        int l = idx & 63, g = (idx>>6)&3, r = idx>>8;
        int j = g*256 + r*64 + l;
        g_wih[idx]  = W_ih[j];
        g_bias[idx] = b_ih[j] + b_hh[j];
    }
    for (int idx = i0; idx < TS_LEN*BTOT; idx += stride){
        int b = idx & (BTOT-1), t = idx >> 9;
        g_tsT[idx] = ts[b*TS_LEN + t];
    }
}

// -------- main: cluster-4 persistent LSTM --------
__global__ void __launch_bounds__(THREADS, 1) __cluster_dims__(CL, 1, 1)
lstm_kernel(const float* __restrict__ Wout){
    extern __shared__ float smem[];
    float* hbuf = smem;                    // [2][256][16] double-buffered full h for this cluster's batches
    float* red  = smem + 2*256*16;         // [256 rows][RSTRIDE] k-split partials

    uint32_t rk; asm("mov.u32 %0, %%cluster_ctarank;" : "=r"(rk));
    int tid = threadIdx.x;
    int l   = tid & 63;                    // hidden-sub-index within this CTA's 64
    int ks  = tid >> 6;                    // k-split group 0..3
    int B0  = (blockIdx.x >> 2) * BT;      // batch base of this cluster
    int bq  = ks * 4;                      // this thread's activation batch sub-range

    for (int i = tid; i < 256*16; i += THREADS) hbuf[i] = 0.f;   // h_0 = 0

    float wih[4], bias[4];
    #pragma unroll
    for (int g = 0; g < 4; ++g){
        wih[g]  = g_wih [(rk*4+g)*64 + l];
        bias[g] = g_bias[(rk*4+g)*64 + l];
    }
    float creg[4] = {0.f,0.f,0.f,0.f};     // c state for (l, bq..bq+3)
    float oacc[4] = {0.f,0.f,0.f,0.f};     // running output dot partials

    const float4* __restrict__ wp_base = g_Wq4 + ((int)rk*256 + ks*KCH)*64 + l;
    const float*  xrow  = g_tsT + B0 + bq;
    const float*  woutp = Wout + (int)rk*64 + l;

    // precompute DSMEM h-broadcast addresses for both buffers x all ranks
    uint32_t hb32 = smem_u32(hbuf);
    uint32_t raddr[2][CL];
    #pragma unroll
    for (int bufn = 0; bufn < 2; ++bufn){
        uint32_t loc = hb32 + (((bufn*256 + (int)rk*64 + l)*16 + bq) << 2);
        #pragma unroll
        for (int dr = 0; dr < CL; ++dr) raddr[bufn][dr] = mapa_r(loc, dr);
    }

    ull* rowp = (ull*)(red + tid*RSTRIDE);

    __syncthreads();

    for (int t = 0; t < TS_LEN; ++t){
        int cur = t & 1, nxt = cur ^ 1;

        // ---- GEMM phase: gates[g][b] partial over k in [ks*64, ks*64+64) ----
        const ulonglong2* hp = (const ulonglong2*)(hbuf + (cur*256 + ks*KCH)*16);
        const float4* wp = wp_base;
        ull acc[4][8];
        #pragma unroll
        for (int g = 0; g < 4; ++g)
            #pragma unroll
            for (int p = 0; p < 8; ++p) acc[g][p] = 0ULL;

        #pragma unroll 4
        for (int kk = 0; kk < KCH; ++kk){
            float4 w = wp[(size_t)kk*64];                 // coalesced LDG.128 (L2-resident)
            ulonglong2 q0 = hp[kk*4+0];                   // warp-uniform LDS.128 (broadcast)
            ulonglong2 q1 = hp[kk*4+1];
            ulonglong2 q2 = hp[kk*4+2];
            ulonglong2 q3 = hp[kk*4+3];
            ull hv[8] = {q0.x,q0.y,q1.x,q1.y,q2.x,q2.y,q3.x,q3.y};
            ull wv[4] = {pack2(w.x,w.x), pack2(w.y,w.y), pack2(w.z,w.z), pack2(w.w,w.w)};
            #pragma unroll
            for (int g = 0; g < 4; ++g)
                #pragma unroll
                for (int p = 0; p < 8; ++p)
                    acc[g][p] = fma2(wv[g], hv[p], acc[g][p]);   // packed f32x2 FMA
        }

        // ---- k-split reduce via smem ----
        #pragma unroll
        for (int g = 0; g < 4; ++g)
            #pragma unroll
            for (int p = 0; p < 8; ++p)
                rowp[g*8 + p] = acc[g][p];
        __syncthreads();

        // ---- activations for this thread's 4 batches ----
        const float* xr = xrow + t*BTOT;
        float xt[4];
        #pragma unroll
        for (int j = 0; j < 4; ++j) xt[j] = xr[j];
        float wo = woutp[t*HD];
        float hout[4];
        #pragma unroll
        for (int j = 0; j < 4; ++j){
            int b = bq + j;
            float gv[4];
            #pragma unroll
            for (int g = 0; g < 4; ++g){
                float s = fmaf(xt[j], wih[g], bias[g]);
                #pragma unroll
                for (int kp = 0; kp < 4; ++kp)
                    s += red[(kp*64 + l)*RSTRIDE + g*16 + b];
                gv[g] = s;
            }
            float c = sigf(gv[1])*creg[j] + sigf(gv[0])*tanha(gv[2]);
            creg[j] = c;
            float h = sigf(gv[3])*tanha(c);
            hout[j] = h;
            oacc[j] = fmaf(h, wo, oacc[j]);               // fused W_out projection
        }

        // ---- broadcast h_new chunk to all 4 cluster CTAs (next buffer) ----
        #pragma unroll
        for (int dr = 0; dr < CL; ++dr){
            asm volatile("st.shared::cluster.v4.f32 [%0], {%1,%2,%3,%4};"
                :: "r"(raddr[nxt][dr]), "f"(hout[0]), "f"(hout[1]), "f"(hout[2]), "f"(hout[3])
                : "memory");
        }
        asm volatile("barrier.cluster.arrive.aligned;" ::: "memory");  // release: orders DSMEM stores
        asm volatile("barrier.cluster.wait.aligned;"   ::: "memory");  // acquire
    }

    // ---- reduce output partials over l within CTA (deterministic order) ----
    __syncthreads();
    #pragma unroll
    for (int j = 0; j < 4; ++j) red[tid*4 + j] = oacc[j];
    __syncthreads();
    if (tid < BT){
        int ksb = tid >> 2, j = tid & 3;
        float s = 0.f;
        for (int ll = 0; ll < 64; ++ll) s += red[(ksb*64 + ll)*4 + j];
        g_part[(int)rk*BTOT + B0 + tid] = s;
    }
}

// -------- finish: combine rank partials + bias --------
__global__ void finish_kernel(const float* __restrict__ b_out, float* __restrict__ out){
    int b = blockIdx.x * blockDim.x + threadIdx.x;
    if (b < BTOT)
        out[b] = b_out[0] + g_part[b] + g_part[BTOT + b] + g_part[2*BTOT + b] + g_part[3*BTOT + b];
}

extern "C" void kernel_launch(void* const* d_in, const int* in_sizes, int n_in,
                              void* d_out, int out_size){
    const float* ts    = (const float*)d_in[0];
    const float* W_ih  = (const float*)d_in[1];
    const float* W_hh  = (const float*)d_in[2];
    const float* b_ih  = (const float*)d_in[3];
    const float* b_hh  = (const float*)d_in[4];
    const float* W_out = (const float*)d_in[5];
    const float* b_out = (const float*)d_in[6];
    float* out = (float*)d_out;

    cudaFuncSetAttribute(lstm_kernel, cudaFuncAttributeMaxDynamicSharedMemorySize, SMEM_BYTES);
    prep_kernel<<<256, 256>>>(ts, W_ih, W_hh, b_ih, b_hh);
    lstm_kernel<<<128, THREADS, SMEM_BYTES>>>(W_out);   // 32 clusters x 4 CTAs
    finish_kernel<<<2, 256>>>(b_out, out);
}